// round 1
// baseline (speedup 1.0000x reference)
#include <cuda_runtime.h>
#include <math.h>

#define BATCH 65536
#define HID   4096
#define RDIM  256
#define EXP   64

// 64 MB scratch for x_proj (allowed: __device__ global, no runtime alloc)
__device__ float g_xproj[BATCH * (size_t)RDIM];

// ---------- packed f32x2 helpers (FFMA2: 2x fp32 FMA throughput on sm_103a) ----------
__device__ __forceinline__ unsigned long long pack2(float x, float y) {
    unsigned long long r;
    asm("mov.b64 %0, {%1, %2};" : "=l"(r) : "f"(x), "f"(y));
    return r;
}
__device__ __forceinline__ void unpack2(unsigned long long v, float& x, float& y) {
    asm("mov.b64 {%0, %1}, %2;" : "=f"(x), "=f"(y) : "l"(v));
}
__device__ __forceinline__ void ffma2(unsigned long long& acc, unsigned long long a, unsigned long long b) {
    asm("fma.rn.f32x2 %0, %1, %2, %0;" : "+l"(acc) : "l"(a), "l"(b));
}

// ============================================================================
// Kernel 1: x_proj = x @ Wp + bp     [65536 x 4096] @ [4096 x 256]
// Tile: 64(M) x 256(N), K-chunk 16, 256 threads, 8x8 per thread (float2 x 4)
// ============================================================================
__global__ void __launch_bounds__(256, 2)
gemm1_kernel(const float* __restrict__ x, const float* __restrict__ Wp,
             const float* __restrict__ bp)
{
    __shared__ float As[16][68];   // transposed A tile, padded
    __shared__ float Bs[16][256];
    __shared__ float bps[256];

    const int tid = threadIdx.x;
    const int m0  = blockIdx.x * 64;
    const int tn  = tid & 31;
    const int tm  = tid >> 5;

    bps[tid] = bp[tid];

    // A loader: row = tid>>2 (0..63), k offset = (tid&3)*4
    const int arow = tid >> 2;
    const int akq  = (tid & 3) * 4;
    const float* xptr = x + (size_t)(m0 + arow) * HID + akq;

    unsigned long long acc[8][4];
#pragma unroll
    for (int i = 0; i < 8; i++)
#pragma unroll
        for (int j = 0; j < 4; j++) acc[i][j] = 0ull;

    float4 aReg;
    float4 bReg[4];

    auto gload = [&](int k0) {
        aReg = *(const float4*)(xptr + k0);
#pragma unroll
        for (int i = 0; i < 4; i++) {
            int fl4 = tid + i * 256;
            int k = fl4 >> 6, c4 = fl4 & 63;
            bReg[i] = *(const float4*)(Wp + (size_t)(k0 + k) * RDIM + c4 * 4);
        }
    };
    auto sstore = [&]() {
        As[akq + 0][arow] = aReg.x;
        As[akq + 1][arow] = aReg.y;
        As[akq + 2][arow] = aReg.z;
        As[akq + 3][arow] = aReg.w;
#pragma unroll
        for (int i = 0; i < 4; i++) {
            int fl4 = tid + i * 256;
            int k = fl4 >> 6, c4 = fl4 & 63;
            *(float4*)&Bs[k][c4 * 4] = bReg[i];
        }
    };
    auto compute = [&]() {
#pragma unroll
        for (int k = 0; k < 16; k++) {
            float4 a0 = *(const float4*)&As[k][tm * 8];
            float4 a1 = *(const float4*)&As[k][tm * 8 + 4];
            float2 b0 = *(const float2*)&Bs[k][tn * 4];
            float2 b1 = *(const float2*)&Bs[k][tn * 4 + 2];
            float2 b2 = *(const float2*)&Bs[k][128 + tn * 4];
            float2 b3 = *(const float2*)&Bs[k][128 + tn * 4 + 2];
            unsigned long long bp0 = pack2(b0.x, b0.y);
            unsigned long long bp1 = pack2(b1.x, b1.y);
            unsigned long long bp2 = pack2(b2.x, b2.y);
            unsigned long long bp3 = pack2(b3.x, b3.y);
            float av[8] = {a0.x, a0.y, a0.z, a0.w, a1.x, a1.y, a1.z, a1.w};
#pragma unroll
            for (int i = 0; i < 8; i++) {
                unsigned long long ap = pack2(av[i], av[i]);
                ffma2(acc[i][0], ap, bp0);
                ffma2(acc[i][1], ap, bp1);
                ffma2(acc[i][2], ap, bp2);
                ffma2(acc[i][3], ap, bp3);
            }
        }
    };

    gload(0); sstore(); __syncthreads();
    for (int k0 = 16; k0 < HID; k0 += 16) {
        gload(k0);
        compute();
        __syncthreads();
        sstore();
        __syncthreads();
    }
    compute();

    // epilogue: + bp, store x_proj
#pragma unroll
    for (int i = 0; i < 8; i++) {
        int row = m0 + tm * 8 + i;
        float o[8];
#pragma unroll
        for (int j = 0; j < 4; j++) unpack2(acc[i][j], o[j * 2], o[j * 2 + 1]);
        int c0 = tn * 4, c1 = 128 + tn * 4;
        float4 v0 = make_float4(o[0] + bps[c0], o[1] + bps[c0 + 1], o[2] + bps[c0 + 2], o[3] + bps[c0 + 3]);
        float4 v1 = make_float4(o[4] + bps[c1], o[5] + bps[c1 + 1], o[6] + bps[c1 + 2], o[7] + bps[c1 + 3]);
        *(float4*)(g_xproj + (size_t)row * RDIM + c0) = v0;
        *(float4*)(g_xproj + (size_t)row * RDIM + c1) = v1;
    }
}

// ============================================================================
// Kernel 2: fused router
//   ut    = [h | x_proj] @ [A ; Bm]           (64x256x512 per block)
//   h_new = h + 0.1*(-h/tau + tanh(ut))
//   logit = h_new @ Wg + bg  (+0.1 at prev_sel)
//   top2 -> softmax -> out
// ============================================================================
// dynamic smem layout (bytes)
#define K2_OFF_TAU 0
#define K2_OFF_BG  1024
#define K2_OFF_AS  1280                      // 16*68*4   = 4352
#define K2_OFF_BS  5632                      // 16*256*4  = 16384
#define K2_OFF_HN  22016                     // 64*257*4  = 65792
#define K2_OFF_WG  87808                     // 256*64*4  = 65536
#define K2_OFF_LG  153344                    // 64*68*4   = 17408
#define K2_SMEM_BYTES 170752

__global__ void __launch_bounds__(256, 1)
router_kernel(const float* __restrict__ h, const int* __restrict__ prev_sel,
              const float* __restrict__ tau,
              const float* __restrict__ Am, const float* __restrict__ Bmm,
              const float* __restrict__ Wg, const float* __restrict__ bg,
              float* __restrict__ out)
{
    extern __shared__ char smemraw[];
    float* staus      = (float*)(smemraw + K2_OFF_TAU);
    float* bgs        = (float*)(smemraw + K2_OFF_BG);
    float (*As)[68]   = reinterpret_cast<float(*)[68]>(smemraw + K2_OFF_AS);
    float (*Bs)[256]  = reinterpret_cast<float(*)[256]>(smemraw + K2_OFF_BS);
    float (*hn)[257]  = reinterpret_cast<float(*)[257]>(smemraw + K2_OFF_HN);
    float (*Wgs)[64]  = reinterpret_cast<float(*)[64]>(smemraw + K2_OFF_WG);
    float (*lg)[68]   = reinterpret_cast<float(*)[68]>(smemraw + K2_OFF_LG);

    const int tid = threadIdx.x;
    const int m0  = blockIdx.x * 64;
    const int tn  = tid & 31;
    const int tm  = tid >> 5;

    staus[tid & 255] = tau[tid & 255];
    if (tid < 64) bgs[tid] = bg[tid];

    const int arow = tid >> 2;
    const int akq  = (tid & 3) * 4;

    unsigned long long acc[8][4];
#pragma unroll
    for (int i = 0; i < 8; i++)
#pragma unroll
        for (int j = 0; j < 4; j++) acc[i][j] = 0ull;

    float4 aReg;
    float4 bReg[4];

    auto gload = [&](int k0) {
        int kk = k0 + akq;   // 0..508, uniform half per chunk
        const float* asrc = (kk < RDIM)
            ? (h + (size_t)(m0 + arow) * RDIM + kk)
            : (g_xproj + (size_t)(m0 + arow) * RDIM + (kk - RDIM));
        aReg = *(const float4*)asrc;
#pragma unroll
        for (int i = 0; i < 4; i++) {
            int fl4 = tid + i * 256;
            int k = fl4 >> 6, c4 = fl4 & 63;
            int kkb = k0 + k;
            const float* bsrc = (kkb < RDIM)
                ? (Am + (size_t)kkb * RDIM)
                : (Bmm + (size_t)(kkb - RDIM) * RDIM);
            bReg[i] = *(const float4*)(bsrc + c4 * 4);
        }
    };
    auto sstore = [&]() {
        As[akq + 0][arow] = aReg.x;
        As[akq + 1][arow] = aReg.y;
        As[akq + 2][arow] = aReg.z;
        As[akq + 3][arow] = aReg.w;
#pragma unroll
        for (int i = 0; i < 4; i++) {
            int fl4 = tid + i * 256;
            int k = fl4 >> 6, c4 = fl4 & 63;
            *(float4*)&Bs[k][c4 * 4] = bReg[i];
        }
    };
    auto compute = [&]() {
#pragma unroll
        for (int k = 0; k < 16; k++) {
            float4 a0 = *(const float4*)&As[k][tm * 8];
            float4 a1 = *(const float4*)&As[k][tm * 8 + 4];
            float2 b0 = *(const float2*)&Bs[k][tn * 4];
            float2 b1 = *(const float2*)&Bs[k][tn * 4 + 2];
            float2 b2 = *(const float2*)&Bs[k][128 + tn * 4];
            float2 b3 = *(const float2*)&Bs[k][128 + tn * 4 + 2];
            unsigned long long bp0 = pack2(b0.x, b0.y);
            unsigned long long bp1 = pack2(b1.x, b1.y);
            unsigned long long bp2 = pack2(b2.x, b2.y);
            unsigned long long bp3 = pack2(b3.x, b3.y);
            float av[8] = {a0.x, a0.y, a0.z, a0.w, a1.x, a1.y, a1.z, a1.w};
#pragma unroll
            for (int i = 0; i < 8; i++) {
                unsigned long long ap = pack2(av[i], av[i]);
                ffma2(acc[i][0], ap, bp0);
                ffma2(acc[i][1], ap, bp1);
                ffma2(acc[i][2], ap, bp2);
                ffma2(acc[i][3], ap, bp3);
            }
        }
    };

    gload(0); sstore(); __syncthreads();
    for (int k0 = 16; k0 < 2 * RDIM; k0 += 16) {
        gload(k0);
        compute();
        __syncthreads();
        sstore();
        __syncthreads();
    }
    compute();

    // ---- CfC epilogue: h_new = h + 0.1*(-h/tau + tanh(ut)) ----
#pragma unroll
    for (int i = 0; i < 8; i++) {
        int r = tm * 8 + i;
        const float* hrow = h + (size_t)(m0 + r) * RDIM;
#pragma unroll
        for (int half = 0; half < 2; half++) {
            int c0 = half * 128 + tn * 4;
            float4 hv = *(const float4*)(hrow + c0);
            float u[4];
            unpack2(acc[i][half * 2 + 0], u[0], u[1]);
            unpack2(acc[i][half * 2 + 1], u[2], u[3]);
            float hva[4] = {hv.x, hv.y, hv.z, hv.w};
#pragma unroll
            for (int jj = 0; jj < 4; jj++) {
                float t = staus[c0 + jj];
                hn[r][c0 + jj] = hva[jj] + 0.1f * (-hva[jj] / t + tanhf(u[jj]));
            }
        }
    }
    __syncthreads();

    // load Wg into smem (contiguous copy, 4096 float4)
#pragma unroll
    for (int i = 0; i < 16; i++) {
        int f = tid + i * 256;
        ((float4*)&Wgs[0][0])[f] = ((const float4*)Wg)[f];
    }
    __syncthreads();

    // ---- logits = h_new @ Wg + bg   (64 rows x 64 experts) ----
    {
        int r2 = tid & 63;
        int cg = tid >> 6;       // 0..3 -> 16 cols each
        float lacc[16];
#pragma unroll
        for (int j = 0; j < 16; j++) lacc[j] = bgs[cg * 16 + j];
#pragma unroll 8
        for (int k = 0; k < RDIM; k++) {
            float a = hn[r2][k];
            const float* wrow = &Wgs[k][cg * 16];
            float4 w0 = *(const float4*)(wrow + 0);
            float4 w1 = *(const float4*)(wrow + 4);
            float4 w2 = *(const float4*)(wrow + 8);
            float4 w3 = *(const float4*)(wrow + 12);
            lacc[0] += a * w0.x;  lacc[1] += a * w0.y;  lacc[2] += a * w0.z;  lacc[3] += a * w0.w;
            lacc[4] += a * w1.x;  lacc[5] += a * w1.y;  lacc[6] += a * w1.z;  lacc[7] += a * w1.w;
            lacc[8] += a * w2.x;  lacc[9] += a * w2.y;  lacc[10] += a * w2.z; lacc[11] += a * w2.w;
            lacc[12] += a * w3.x; lacc[13] += a * w3.y; lacc[14] += a * w3.z; lacc[15] += a * w3.w;
        }
        float* lrow = &lg[r2][cg * 16];
        *(float4*)(lrow + 0)  = make_float4(lacc[0], lacc[1], lacc[2], lacc[3]);
        *(float4*)(lrow + 4)  = make_float4(lacc[4], lacc[5], lacc[6], lacc[7]);
        *(float4*)(lrow + 8)  = make_float4(lacc[8], lacc[9], lacc[10], lacc[11]);
        *(float4*)(lrow + 12) = make_float4(lacc[12], lacc[13], lacc[14], lacc[15]);
    }
    __syncthreads();

    // ---- temporal bias + top-2 (lax.top_k tie-break: lower index) + softmax ----
    if (tid < 64) {
        int grow = m0 + tid;
        int p0 = prev_sel[grow * 2 + 0];
        int p1 = prev_sel[grow * 2 + 1];
        float b1 = -1e30f, b2 = -1e30f;
        int i1 = 0, i2 = 0;
#pragma unroll 8
        for (int e = 0; e < EXP; e++) {
            float v = lg[tid][e];
            if (e == p0 || e == p1) v += 0.1f;
            if (v > b1) { b2 = b1; i2 = i1; b1 = v; i1 = e; }
            else if (v > b2) { b2 = v; i2 = e; }
        }
        float ex = expf(b2 - b1);
        float s  = 1.0f + ex;
        float w1 = 1.0f / s;
        float w2 = ex / s;
        out[grow * 2 + 0] = (float)i1;
        out[grow * 2 + 1] = (float)i2;
        out[2 * BATCH + grow * 2 + 0] = w1;
        out[2 * BATCH + grow * 2 + 1] = w2;
    }
}

extern "C" void kernel_launch(void* const* d_in, const int* in_sizes, int n_in,
                              void* d_out, int out_size)
{
    const float* x        = (const float*)d_in[0];
    const float* h        = (const float*)d_in[1];
    const int*   prev_sel = (const int*)d_in[2];
    const float* Wp       = (const float*)d_in[3];
    const float* bp       = (const float*)d_in[4];
    const float* tau      = (const float*)d_in[5];
    const float* Am       = (const float*)d_in[6];
    const float* Bmm      = (const float*)d_in[7];
    const float* Wg       = (const float*)d_in[8];
    const float* bg       = (const float*)d_in[9];
    float* out = (float*)d_out;

    cudaFuncSetAttribute(router_kernel, cudaFuncAttributeMaxDynamicSharedMemorySize,
                         K2_SMEM_BYTES);

    gemm1_kernel<<<BATCH / 64, 256>>>(x, Wp, bp);
    router_kernel<<<BATCH / 64, 256, K2_SMEM_BYTES>>>(h, prev_sel, tau, Am, Bmm, Wg, bg, out);
}

// round 3
// speedup vs baseline: 1.9779x; 1.9779x over previous
#include <cuda_runtime.h>
#include <cuda_bf16.h>
#include <math.h>
#include <stdint.h>

#define BATCH 65536
#define HID   4096
#define RDIM  256
#define EXP   64
#define KCH   64
#define NCHUNK 64

// ------------------------- device scratch -------------------------
__device__ float g_xproj[BATCH * (size_t)RDIM];     // 64 MB
__device__ uint4 g_Bhi[2 * 64 * 1024];              // 2 MB: [nb][chunk] 16KB swizzled tiles
__device__ uint4 g_Blo[2 * 64 * 1024];              // 2 MB

// ------------------------- helpers -------------------------
__device__ __forceinline__ uint32_t smem_u32(const void* p) {
    uint32_t a;
    asm("{ .reg .u64 t; cvta.to.shared.u64 t, %1; cvt.u32.u64 %0, t; }" : "=r"(a) : "l"(p));
    return a;
}
// pack: low half = bf16(a), high half = bf16(b)
__device__ __forceinline__ uint32_t cvt_bf16x2(float a, float b) {
    uint32_t r;
    asm("cvt.rn.bf16x2.f32 %0, %1, %2;" : "=r"(r) : "f"(b), "f"(a));
    return r;
}
__device__ __forceinline__ void split2(float a, float b, uint32_t& hi, uint32_t& lo) {
    hi = cvt_bf16x2(a, b);
    float ha = __uint_as_float(hi << 16);
    float hb = __uint_as_float(hi & 0xffff0000u);
    lo = cvt_bf16x2(a - ha, b - hb);
}
__device__ __forceinline__ void ldsm4(uint32_t* r, uint32_t addr) {
    asm volatile("ldmatrix.sync.aligned.m8n8.x4.shared.b16 {%0,%1,%2,%3}, [%4];"
        : "=r"(r[0]), "=r"(r[1]), "=r"(r[2]), "=r"(r[3]) : "r"(addr));
}
__device__ __forceinline__ void mma_bf16(float* d, const uint32_t* a, const uint32_t* b) {
    asm volatile("mma.sync.aligned.m16n8k16.row.col.f32.bf16.bf16.f32 "
        "{%0,%1,%2,%3}, {%4,%5,%6,%7}, {%8,%9}, {%0,%1,%2,%3};"
        : "+f"(d[0]), "+f"(d[1]), "+f"(d[2]), "+f"(d[3])
        : "r"(a[0]), "r"(a[1]), "r"(a[2]), "r"(a[3]), "r"(b[0]), "r"(b[1]));
}
__device__ __forceinline__ void cpasync16(uint32_t dst, const void* src) {
    asm volatile("cp.async.cg.shared.global [%0], [%1], 16;" :: "r"(dst), "l"(src));
}
__device__ __forceinline__ void cpcommit() { asm volatile("cp.async.commit_group;" ::: "memory"); }
template<int N> __device__ __forceinline__ void cpwait() {
    asm volatile("cp.async.wait_group %0;" :: "n"(N) : "memory");
}
// packed f32x2 helpers (router)
__device__ __forceinline__ unsigned long long pack2(float x, float y) {
    unsigned long long r;
    asm("mov.b64 %0, {%1, %2};" : "=l"(r) : "f"(x), "f"(y));
    return r;
}
__device__ __forceinline__ void unpack2(unsigned long long v, float& x, float& y) {
    asm("mov.b64 {%0, %1}, %2;" : "=f"(x), "=f"(y) : "l"(v));
}
__device__ __forceinline__ void ffma2(unsigned long long& acc, unsigned long long a, unsigned long long b) {
    asm("fma.rn.f32x2 %0, %1, %2, %0;" : "+l"(acc) : "l"(a), "l"(b));
}

// ============================================================================
// Prep: Wp [4096,256] fp32 -> bf16 hi/lo, transposed [n][k], SW128-swizzled
// tile images of 128 rows x 128B, per (n-block, k-chunk).
// ============================================================================
__global__ void prep_B_kernel(const float* __restrict__ Wp)
{
    int idx = blockIdx.x * 256 + threadIdx.x;   // 524288 threads, 2 k each
    int n  = idx & 255;
    int kp = idx >> 8;
    int k0 = kp * 2;
    int c  = k0 >> 6;
    int kl = k0 & 63;
    int nb = n >> 7;
    int r  = n & 127;
    float f0 = Wp[(size_t)k0 * RDIM + n];
    float f1 = Wp[(size_t)(k0 + 1) * RDIM + n];
    uint32_t hi, lo;
    split2(f0, f1, hi, lo);
    uint32_t off = (uint32_t)(r * 128 + kl * 2);
    off ^= (off >> 3) & 0x70;
    size_t tile = (size_t)(nb * 64 + c) * 16384;
    *(uint32_t*)((char*)g_Bhi + tile + off) = hi;
    *(uint32_t*)((char*)g_Blo + tile + off) = lo;
}

// ============================================================================
// GEMM1 via mma.sync bf16 (3-pass hi/lo): x_proj = x @ Wp + bp
// CTA: 128(M) x 128(N), grid (512, 2), 256 threads (8 warps, warp tile 32x64)
// smem: [0,1024) bp; A_hi @1024 (16K); A_lo @17408 (16K); B stages @33792:
//       stage s: B_hi (16K) + B_lo (16K); total 99328 B.
// ============================================================================
#define AHI_OFF 1024
#define ALO_OFF (1024 + 16384)
#define BST_OFF(s) (1024 + 32768 + (s) * 32768)
#define G1_SMEM 99328

__global__ void __launch_bounds__(256, 1)
gemm1_mma_kernel(const float* __restrict__ x, const float* __restrict__ bp)
{
    extern __shared__ __align__(1024) char sm[];
    const uint32_t sb = smem_u32(sm);
    float* sbp = (float*)sm;
    const int tid  = threadIdx.x;
    const int lane = tid & 31;
    const int wid  = tid >> 5;
    const int wm   = wid & 3;          // 4 warps along M (32 rows each)
    const int wn   = wid >> 2;         // 2 warps along N (64 cols each)
    const int mb   = blockIdx.x;
    const int ny   = blockIdx.y;
    const size_t m0 = (size_t)mb * 128;

    if (tid < 128) sbp[tid] = bp[ny * 128 + tid];

    // ---- per-lane ldmatrix address precomputation ----
    const int j = lane >> 3;
    // A: x4 matrices (m0-7,k0-7),(m8-15,k0-7),(m0-7,k8-15),(m8-15,k8-15)
    const int a_rloc = (lane & 7) + (j & 1) * 8;
    const int a_kadd = (j >> 1) * 16;
    const int a_row0 = wm * 32 + a_rloc;
    const uint32_t a_xp    = (uint32_t)((a_row0 & 7) << 4);
    const uint32_t aHiBase = sb + AHI_OFF + a_row0 * 128;
    // B: x4 matrices (n0-7,k0-7),(n0-7,k8-15),(n8-15,k0-7),(n8-15,k8-15)
    const int b_nloc = (lane & 7) + (j >> 1) * 8;
    const int b_kadd = (j & 1) * 16;
    const uint32_t b_xp = (uint32_t)((lane & 7) << 4);
    uint32_t bRow[4];
#pragma unroll
    for (int p = 0; p < 4; p++) bRow[p] = (uint32_t)((wn * 64 + p * 16 + b_nloc) * 128);

    // ---- A gload/sstore mapping: q fixed per thread, r = r0 + 16*i ----
    const int r0 = tid >> 4;           // 0..15
    const int q  = tid & 15;           // float4 index within 64-float row
    const float* xbase = x + (m0 + r0) * HID + q * 4;
    const uint32_t soff0 = (uint32_t)(r0 * 128 + (((q * 8)) ^ ((r0 & 7) << 4)));

    float acc[2][8][4];
#pragma unroll
    for (int a = 0; a < 2; a++)
#pragma unroll
        for (int b = 0; b < 8; b++)
#pragma unroll
            for (int d = 0; d < 4; d++) acc[a][b][d] = 0.0f;

    float4 af[8];

    auto gloadA = [&](int c) {
#pragma unroll
        for (int i = 0; i < 8; i++)
            af[i] = *(const float4*)(xbase + (size_t)i * 16 * HID + c * KCH);
    };
    auto sstoreA = [&]() {
#pragma unroll
        for (int i = 0; i < 8; i++) {
            uint32_t h01, l01, h23, l23;
            split2(af[i].x, af[i].y, h01, l01);
            split2(af[i].z, af[i].w, h23, l23);
            uint32_t off = soff0 + i * 2048;
            *(uint2*)(sm + AHI_OFF + off) = make_uint2(h01, h23);
            *(uint2*)(sm + ALO_OFF + off) = make_uint2(l01, l23);
        }
    };
    auto cpB = [&](int c, int s) {
        const uint4* srcH = g_Bhi + (size_t)(ny * 64 + c) * 1024;
        const uint4* srcL = g_Blo + (size_t)(ny * 64 + c) * 1024;
        uint32_t dst = sb + BST_OFF(s);
#pragma unroll
        for (int i = 0; i < 4; i++) {
            int e = tid + i * 256;
            cpasync16(dst + e * 16, srcH + e);
            cpasync16(dst + 16384 + e * 16, srcL + e);
        }
        cpcommit();
    };
    auto compute = [&](int s) {
        const uint32_t sBhi = sb + BST_OFF(s);
#pragma unroll
        for (int ks = 0; ks < 4; ks++) {
            const uint32_t kb = ks * 32;
            const uint32_t akt = (kb + a_kadd) ^ a_xp;
            uint32_t aH[2][4], aL[2][4];
            ldsm4(aH[0], aHiBase + akt);
            ldsm4(aH[1], aHiBase + 2048 + akt);
            ldsm4(aL[0], aHiBase + 16384 + akt);
            ldsm4(aL[1], aHiBase + 16384 + 2048 + akt);
            const uint32_t bkt = (kb + b_kadd) ^ b_xp;
            uint32_t bH[8][2], bL[8][2];
#pragma unroll
            for (int p = 0; p < 4; p++) {
                uint32_t r[4];
                ldsm4(r, sBhi + bRow[p] + bkt);
                bH[2 * p][0] = r[0]; bH[2 * p][1] = r[1];
                bH[2 * p + 1][0] = r[2]; bH[2 * p + 1][1] = r[3];
                ldsm4(r, sBhi + 16384 + bRow[p] + bkt);
                bL[2 * p][0] = r[0]; bL[2 * p][1] = r[1];
                bL[2 * p + 1][0] = r[2]; bL[2 * p + 1][1] = r[3];
            }
#pragma unroll
            for (int mt = 0; mt < 2; mt++) {
#pragma unroll
                for (int nt = 0; nt < 8; nt++) {
                    mma_bf16(acc[mt][nt], aH[mt], bH[nt]);
                    mma_bf16(acc[mt][nt], aH[mt], bL[nt]);
                    mma_bf16(acc[mt][nt], aL[mt], bH[nt]);
                }
            }
        }
    };

    // ---- pipelined main loop ----
    gloadA(0);
    cpB(0, 0);
    sstoreA();

    for (int c = 0; c < NCHUNK; c++) {
        if (c < NCHUNK - 1) {
            gloadA(c + 1);
            cpB(c + 1, (c + 1) & 1);
        }
        if (c < NCHUNK - 1) cpwait<1>(); else cpwait<0>();
        __syncthreads();
        compute(c & 1);
        __syncthreads();
        if (c < NCHUNK - 1) sstoreA();
    }

    // ---- epilogue: + bp -> g_xproj ----
#pragma unroll
    for (int mt = 0; mt < 2; mt++) {
#pragma unroll
        for (int nt = 0; nt < 8; nt++) {
            int row  = (int)m0 + wm * 32 + mt * 16 + (lane >> 2);
            int coll = wn * 64 + nt * 8 + (lane & 3) * 2;     // within 128-col block
            int gcol = ny * 128 + coll;
            float b0 = sbp[coll], b1 = sbp[coll + 1];
            float2 v0 = make_float2(acc[mt][nt][0] + b0, acc[mt][nt][1] + b1);
            float2 v1 = make_float2(acc[mt][nt][2] + b0, acc[mt][nt][3] + b1);
            *(float2*)(g_xproj + (size_t)row * RDIM + gcol) = v0;
            *(float2*)(g_xproj + (size_t)(row + 8) * RDIM + gcol) = v1;
        }
    }
}

// ============================================================================
// Kernel 2: fused router (FFMA2 path, unchanged)
// ============================================================================
#define K2_OFF_TAU 0
#define K2_OFF_BG  1024
#define K2_OFF_AS  1280
#define K2_OFF_BS  5632
#define K2_OFF_HN  22016
#define K2_OFF_WG  87808
#define K2_OFF_LG  153344
#define K2_SMEM_BYTES 170752

__global__ void __launch_bounds__(256, 1)
router_kernel(const float* __restrict__ h, const int* __restrict__ prev_sel,
              const float* __restrict__ tau,
              const float* __restrict__ Am, const float* __restrict__ Bmm,
              const float* __restrict__ Wg, const float* __restrict__ bg,
              float* __restrict__ out)
{
    extern __shared__ char smemraw[];
    float* staus      = (float*)(smemraw + K2_OFF_TAU);
    float* bgs        = (float*)(smemraw + K2_OFF_BG);
    float (*As)[68]   = reinterpret_cast<float(*)[68]>(smemraw + K2_OFF_AS);
    float (*Bs)[256]  = reinterpret_cast<float(*)[256]>(smemraw + K2_OFF_BS);
    float (*hn)[257]  = reinterpret_cast<float(*)[257]>(smemraw + K2_OFF_HN);
    float (*Wgs)[64]  = reinterpret_cast<float(*)[64]>(smemraw + K2_OFF_WG);
    float (*lg)[68]   = reinterpret_cast<float(*)[68]>(smemraw + K2_OFF_LG);

    const int tid = threadIdx.x;
    const int m0  = blockIdx.x * 64;
    const int tn  = tid & 31;
    const int tm  = tid >> 5;

    staus[tid & 255] = tau[tid & 255];
    if (tid < 64) bgs[tid] = bg[tid];

    const int arow = tid >> 2;
    const int akq  = (tid & 3) * 4;

    unsigned long long acc[8][4];
#pragma unroll
    for (int i = 0; i < 8; i++)
#pragma unroll
        for (int j = 0; j < 4; j++) acc[i][j] = 0ull;

    float4 aReg;
    float4 bReg[4];

    auto gload = [&](int k0) {
        int kk = k0 + akq;
        const float* asrc = (kk < RDIM)
            ? (h + (size_t)(m0 + arow) * RDIM + kk)
            : (g_xproj + (size_t)(m0 + arow) * RDIM + (kk - RDIM));
        aReg = *(const float4*)asrc;
#pragma unroll
        for (int i = 0; i < 4; i++) {
            int fl4 = tid + i * 256;
            int k = fl4 >> 6, c4 = fl4 & 63;
            int kkb = k0 + k;
            const float* bsrc = (kkb < RDIM)
                ? (Am + (size_t)kkb * RDIM)
                : (Bmm + (size_t)(kkb - RDIM) * RDIM);
            bReg[i] = *(const float4*)(bsrc + c4 * 4);
        }
    };
    auto sstore = [&]() {
        As[akq + 0][arow] = aReg.x;
        As[akq + 1][arow] = aReg.y;
        As[akq + 2][arow] = aReg.z;
        As[akq + 3][arow] = aReg.w;
#pragma unroll
        for (int i = 0; i < 4; i++) {
            int fl4 = tid + i * 256;
            int k = fl4 >> 6, c4 = fl4 & 63;
            *(float4*)&Bs[k][c4 * 4] = bReg[i];
        }
    };
    auto compute = [&]() {
#pragma unroll
        for (int k = 0; k < 16; k++) {
            float4 a0 = *(const float4*)&As[k][tm * 8];
            float4 a1 = *(const float4*)&As[k][tm * 8 + 4];
            float2 b0 = *(const float2*)&Bs[k][tn * 4];
            float2 b1 = *(const float2*)&Bs[k][tn * 4 + 2];
            float2 b2 = *(const float2*)&Bs[k][128 + tn * 4];
            float2 b3 = *(const float2*)&Bs[k][128 + tn * 4 + 2];
            unsigned long long bp0 = pack2(b0.x, b0.y);
            unsigned long long bp1 = pack2(b1.x, b1.y);
            unsigned long long bp2 = pack2(b2.x, b2.y);
            unsigned long long bp3 = pack2(b3.x, b3.y);
            float av[8] = {a0.x, a0.y, a0.z, a0.w, a1.x, a1.y, a1.z, a1.w};
#pragma unroll
            for (int i = 0; i < 8; i++) {
                unsigned long long ap = pack2(av[i], av[i]);
                ffma2(acc[i][0], ap, bp0);
                ffma2(acc[i][1], ap, bp1);
                ffma2(acc[i][2], ap, bp2);
                ffma2(acc[i][3], ap, bp3);
            }
        }
    };

    gload(0); sstore(); __syncthreads();
    for (int k0 = 16; k0 < 2 * RDIM; k0 += 16) {
        gload(k0);
        compute();
        __syncthreads();
        sstore();
        __syncthreads();
    }
    compute();

#pragma unroll
    for (int i = 0; i < 8; i++) {
        int r = tm * 8 + i;
        const float* hrow = h + (size_t)(m0 + r) * RDIM;
#pragma unroll
        for (int half = 0; half < 2; half++) {
            int c0 = half * 128 + tn * 4;
            float4 hv = *(const float4*)(hrow + c0);
            float u[4];
            unpack2(acc[i][half * 2 + 0], u[0], u[1]);
            unpack2(acc[i][half * 2 + 1], u[2], u[3]);
            float hva[4] = {hv.x, hv.y, hv.z, hv.w};
#pragma unroll
            for (int jj = 0; jj < 4; jj++) {
                float t = staus[c0 + jj];
                hn[r][c0 + jj] = hva[jj] + 0.1f * (-hva[jj] / t + tanhf(u[jj]));
            }
        }
    }
    __syncthreads();

#pragma unroll
    for (int i = 0; i < 16; i++) {
        int f = tid + i * 256;
        ((float4*)&Wgs[0][0])[f] = ((const float4*)Wg)[f];
    }
    __syncthreads();

    {
        int r2 = tid & 63;
        int cg = tid >> 6;
        float lacc[16];
#pragma unroll
        for (int j = 0; j < 16; j++) lacc[j] = bgs[cg * 16 + j];
#pragma unroll 8
        for (int k = 0; k < RDIM; k++) {
            float a = hn[r2][k];
            const float* wrow = &Wgs[k][cg * 16];
            float4 w0 = *(const float4*)(wrow + 0);
            float4 w1 = *(const float4*)(wrow + 4);
            float4 w2 = *(const float4*)(wrow + 8);
            float4 w3 = *(const float4*)(wrow + 12);
            lacc[0] += a * w0.x;  lacc[1] += a * w0.y;  lacc[2] += a * w0.z;  lacc[3] += a * w0.w;
            lacc[4] += a * w1.x;  lacc[5] += a * w1.y;  lacc[6] += a * w1.z;  lacc[7] += a * w1.w;
            lacc[8] += a * w2.x;  lacc[9] += a * w2.y;  lacc[10] += a * w2.z; lacc[11] += a * w2.w;
            lacc[12] += a * w3.x; lacc[13] += a * w3.y; lacc[14] += a * w3.z; lacc[15] += a * w3.w;
        }
        float* lrow = &lg[r2][cg * 16];
        *(float4*)(lrow + 0)  = make_float4(lacc[0], lacc[1], lacc[2], lacc[3]);
        *(float4*)(lrow + 4)  = make_float4(lacc[4], lacc[5], lacc[6], lacc[7]);
        *(float4*)(lrow + 8)  = make_float4(lacc[8], lacc[9], lacc[10], lacc[11]);
        *(float4*)(lrow + 12) = make_float4(lacc[12], lacc[13], lacc[14], lacc[15]);
    }
    __syncthreads();

    if (tid < 64) {
        int grow = m0 + tid;
        int p0 = prev_sel[grow * 2 + 0];
        int p1 = prev_sel[grow * 2 + 1];
        float b1 = -1e30f, b2 = -1e30f;
        int i1 = 0, i2 = 0;
#pragma unroll 8
        for (int e = 0; e < EXP; e++) {
            float v = lg[tid][e];
            if (e == p0 || e == p1) v += 0.1f;
            if (v > b1) { b2 = b1; i2 = i1; b1 = v; i1 = e; }
            else if (v > b2) { b2 = v; i2 = e; }
        }
        float ex = expf(b2 - b1);
        float s  = 1.0f + ex;
        float w1 = 1.0f / s;
        float w2 = ex / s;
        out[grow * 2 + 0] = (float)i1;
        out[grow * 2 + 1] = (float)i2;
        out[2 * BATCH + grow * 2 + 0] = w1;
        out[2 * BATCH + grow * 2 + 1] = w2;
    }
}

extern "C" void kernel_launch(void* const* d_in, const int* in_sizes, int n_in,
                              void* d_out, int out_size)
{
    const float* x        = (const float*)d_in[0];
    const float* h        = (const float*)d_in[1];
    const int*   prev_sel = (const int*)d_in[2];
    const float* Wp       = (const float*)d_in[3];
    const float* bp       = (const float*)d_in[4];
    const float* tau      = (const float*)d_in[5];
    const float* Am       = (const float*)d_in[6];
    const float* Bmm      = (const float*)d_in[7];
    const float* Wg       = (const float*)d_in[8];
    const float* bg       = (const float*)d_in[9];
    float* out = (float*)d_out;

    cudaFuncSetAttribute(gemm1_mma_kernel, cudaFuncAttributeMaxDynamicSharedMemorySize, G1_SMEM);
    cudaFuncSetAttribute(router_kernel, cudaFuncAttributeMaxDynamicSharedMemorySize, K2_SMEM_BYTES);

    prep_B_kernel<<<2048, 256>>>(Wp);
    gemm1_mma_kernel<<<dim3(512, 2), 256, G1_SMEM>>>(x, bp);
    router_kernel<<<BATCH / 64, 256, K2_SMEM_BYTES>>>(h, prev_sel, tau, Am, Bmm, Wg, bg, out);
}

// round 4
// speedup vs baseline: 2.2804x; 1.1529x over previous
#include <cuda_runtime.h>
#include <cuda_bf16.h>
#include <math.h>
#include <stdint.h>

#define BATCH 65536
#define HID   4096
#define RDIM  256
#define EXP   64
#define KCH   64
#define NCHUNK 64

// ------------------------- device scratch -------------------------
__device__ float g_xproj[BATCH * (size_t)RDIM];     // 64 MB
__device__ uint4 g_Bhi[2 * 64 * 1024];              // 2 MB: [nb][chunk] 16KB swizzled tiles (Wp)
__device__ uint4 g_Blo[2 * 64 * 1024];              // 2 MB
__device__ uint4 g_Rhi[16 * 1024];                  // 256 KB: [nb][chunk 0..7] tiles ([A;Bm])
__device__ uint4 g_Rlo[16 * 1024];                  // 256 KB

// ------------------------- helpers -------------------------
__device__ __forceinline__ uint32_t smem_u32(const void* p) {
    uint32_t a;
    asm("{ .reg .u64 t; cvta.to.shared.u64 t, %1; cvt.u32.u64 %0, t; }" : "=r"(a) : "l"(p));
    return a;
}
// pack: low half = bf16(a), high half = bf16(b)
__device__ __forceinline__ uint32_t cvt_bf16x2(float a, float b) {
    uint32_t r;
    asm("cvt.rn.bf16x2.f32 %0, %1, %2;" : "=r"(r) : "f"(b), "f"(a));
    return r;
}
__device__ __forceinline__ void split2(float a, float b, uint32_t& hi, uint32_t& lo) {
    hi = cvt_bf16x2(a, b);
    float ha = __uint_as_float(hi << 16);
    float hb = __uint_as_float(hi & 0xffff0000u);
    lo = cvt_bf16x2(a - ha, b - hb);
}
__device__ __forceinline__ void ldsm4(uint32_t* r, uint32_t addr) {
    asm volatile("ldmatrix.sync.aligned.m8n8.x4.shared.b16 {%0,%1,%2,%3}, [%4];"
        : "=r"(r[0]), "=r"(r[1]), "=r"(r[2]), "=r"(r[3]) : "r"(addr));
}
__device__ __forceinline__ void mma_bf16(float* d, const uint32_t* a, const uint32_t* b) {
    asm volatile("mma.sync.aligned.m16n8k16.row.col.f32.bf16.bf16.f32 "
        "{%0,%1,%2,%3}, {%4,%5,%6,%7}, {%8,%9}, {%0,%1,%2,%3};"
        : "+f"(d[0]), "+f"(d[1]), "+f"(d[2]), "+f"(d[3])
        : "r"(a[0]), "r"(a[1]), "r"(a[2]), "r"(a[3]), "r"(b[0]), "r"(b[1]));
}
__device__ __forceinline__ void cpasync16(uint32_t dst, const void* src) {
    asm volatile("cp.async.cg.shared.global [%0], [%1], 16;" :: "r"(dst), "l"(src));
}
__device__ __forceinline__ void cpcommit() { asm volatile("cp.async.commit_group;" ::: "memory"); }
template<int N> __device__ __forceinline__ void cpwait() {
    asm volatile("cp.async.wait_group %0;" :: "n"(N) : "memory");
}

// ============================================================================
// Prep: Wp [4096,256] fp32 -> bf16 hi/lo transposed [n][k] SW128 tile images
// ============================================================================
__global__ void prep_B_kernel(const float* __restrict__ Wp)
{
    int idx = blockIdx.x * 256 + threadIdx.x;
    int n  = idx & 255;
    int kp = idx >> 8;
    int k0 = kp * 2;
    int c  = k0 >> 6;
    int kl = k0 & 63;
    int nb = n >> 7;
    int r  = n & 127;
    float f0 = Wp[(size_t)k0 * RDIM + n];
    float f1 = Wp[(size_t)(k0 + 1) * RDIM + n];
    uint32_t hi, lo;
    split2(f0, f1, hi, lo);
    uint32_t off = (uint32_t)(r * 128 + kl * 2);
    off ^= (off >> 3) & 0x70;
    size_t tile = (size_t)(nb * 64 + c) * 16384;
    *(uint32_t*)((char*)g_Bhi + tile + off) = hi;
    *(uint32_t*)((char*)g_Blo + tile + off) = lo;
}

// ============================================================================
// Prep: [A;Bm] (512x256) fp32 -> bf16 hi/lo transposed [n][k] SW128 tiles
// ============================================================================
__global__ void prep_R_kernel(const float* __restrict__ Am, const float* __restrict__ Bmm)
{
    int idx = blockIdx.x * 256 + threadIdx.x;   // 65536 threads, 2 k each
    int n  = idx & 255;
    int kp = idx >> 8;                          // 0..255
    int k0 = kp * 2;                            // 0..510
    float f0, f1;
    if (k0 < RDIM) {
        f0 = Am[(size_t)k0 * RDIM + n];
        f1 = Am[(size_t)(k0 + 1) * RDIM + n];
    } else {
        f0 = Bmm[(size_t)(k0 - RDIM) * RDIM + n];
        f1 = Bmm[(size_t)(k0 + 1 - RDIM) * RDIM + n];
    }
    uint32_t hi, lo;
    split2(f0, f1, hi, lo);
    int c  = k0 >> 6;                           // 0..7
    int kl = k0 & 63;
    int nb = n >> 7;
    int r  = n & 127;
    uint32_t off = (uint32_t)(r * 128 + kl * 2);
    off ^= (off >> 3) & 0x70;
    size_t tile = (size_t)(nb * 8 + c) * 16384;
    *(uint32_t*)((char*)g_Rhi + tile + off) = hi;
    *(uint32_t*)((char*)g_Rlo + tile + off) = lo;
}

// ============================================================================
// GEMM1 via mma.sync bf16 (3-pass hi/lo): x_proj = x @ Wp + bp
// (unchanged from round 3)
// ============================================================================
#define AHI_OFF 1024
#define ALO_OFF (1024 + 16384)
#define BST_OFF(s) (1024 + 32768 + (s) * 32768)
#define G1_SMEM 99328

__global__ void __launch_bounds__(256, 1)
gemm1_mma_kernel(const float* __restrict__ x, const float* __restrict__ bp)
{
    extern __shared__ __align__(1024) char sm[];
    const uint32_t sb = smem_u32(sm);
    float* sbp = (float*)sm;
    const int tid  = threadIdx.x;
    const int lane = tid & 31;
    const int wid  = tid >> 5;
    const int wm   = wid & 3;
    const int wn   = wid >> 2;
    const int mb   = blockIdx.x;
    const int ny   = blockIdx.y;
    const size_t m0 = (size_t)mb * 128;

    if (tid < 128) sbp[tid] = bp[ny * 128 + tid];

    const int j = lane >> 3;
    const int a_rloc = (lane & 7) + (j & 1) * 8;
    const int a_kadd = (j >> 1) * 16;
    const int a_row0 = wm * 32 + a_rloc;
    const uint32_t a_xp    = (uint32_t)((a_row0 & 7) << 4);
    const uint32_t aHiBase = sb + AHI_OFF + a_row0 * 128;
    const int b_nloc = (lane & 7) + (j >> 1) * 8;
    const int b_kadd = (j & 1) * 16;
    const uint32_t b_xp = (uint32_t)((lane & 7) << 4);
    uint32_t bRow[4];
#pragma unroll
    for (int p = 0; p < 4; p++) bRow[p] = (uint32_t)((wn * 64 + p * 16 + b_nloc) * 128);

    const int r0 = tid >> 4;
    const int q  = tid & 15;
    const float* xbase = x + (m0 + r0) * HID + q * 4;
    const uint32_t soff0 = (uint32_t)(r0 * 128 + (((q * 8)) ^ ((r0 & 7) << 4)));

    float acc[2][8][4];
#pragma unroll
    for (int a = 0; a < 2; a++)
#pragma unroll
        for (int b = 0; b < 8; b++)
#pragma unroll
            for (int d = 0; d < 4; d++) acc[a][b][d] = 0.0f;

    float4 af[8];

    auto gloadA = [&](int c) {
#pragma unroll
        for (int i = 0; i < 8; i++)
            af[i] = *(const float4*)(xbase + (size_t)i * 16 * HID + c * KCH);
    };
    auto sstoreA = [&]() {
#pragma unroll
        for (int i = 0; i < 8; i++) {
            uint32_t h01, l01, h23, l23;
            split2(af[i].x, af[i].y, h01, l01);
            split2(af[i].z, af[i].w, h23, l23);
            uint32_t off = soff0 + i * 2048;
            *(uint2*)(sm + AHI_OFF + off) = make_uint2(h01, h23);
            *(uint2*)(sm + ALO_OFF + off) = make_uint2(l01, l23);
        }
    };
    auto cpB = [&](int c, int s) {
        const uint4* srcH = g_Bhi + (size_t)(ny * 64 + c) * 1024;
        const uint4* srcL = g_Blo + (size_t)(ny * 64 + c) * 1024;
        uint32_t dst = sb + BST_OFF(s);
#pragma unroll
        for (int i = 0; i < 4; i++) {
            int e = tid + i * 256;
            cpasync16(dst + e * 16, srcH + e);
            cpasync16(dst + 16384 + e * 16, srcL + e);
        }
        cpcommit();
    };
    auto compute = [&](int s) {
        const uint32_t sBhi = sb + BST_OFF(s);
#pragma unroll
        for (int ks = 0; ks < 4; ks++) {
            const uint32_t kb = ks * 32;
            const uint32_t akt = (kb + a_kadd) ^ a_xp;
            uint32_t aH[2][4], aL[2][4];
            ldsm4(aH[0], aHiBase + akt);
            ldsm4(aH[1], aHiBase + 2048 + akt);
            ldsm4(aL[0], aHiBase + 16384 + akt);
            ldsm4(aL[1], aHiBase + 16384 + 2048 + akt);
            const uint32_t bkt = (kb + b_kadd) ^ b_xp;
            uint32_t bH[8][2], bL[8][2];
#pragma unroll
            for (int p = 0; p < 4; p++) {
                uint32_t r[4];
                ldsm4(r, sBhi + bRow[p] + bkt);
                bH[2 * p][0] = r[0]; bH[2 * p][1] = r[1];
                bH[2 * p + 1][0] = r[2]; bH[2 * p + 1][1] = r[3];
                ldsm4(r, sBhi + 16384 + bRow[p] + bkt);
                bL[2 * p][0] = r[0]; bL[2 * p][1] = r[1];
                bL[2 * p + 1][0] = r[2]; bL[2 * p + 1][1] = r[3];
            }
#pragma unroll
            for (int mt = 0; mt < 2; mt++) {
#pragma unroll
                for (int nt = 0; nt < 8; nt++) {
                    mma_bf16(acc[mt][nt], aH[mt], bH[nt]);
                    mma_bf16(acc[mt][nt], aH[mt], bL[nt]);
                    mma_bf16(acc[mt][nt], aL[mt], bH[nt]);
                }
            }
        }
    };

    gloadA(0);
    cpB(0, 0);
    sstoreA();

    for (int c = 0; c < NCHUNK; c++) {
        if (c < NCHUNK - 1) {
            gloadA(c + 1);
            cpB(c + 1, (c + 1) & 1);
        }
        if (c < NCHUNK - 1) cpwait<1>(); else cpwait<0>();
        __syncthreads();
        compute(c & 1);
        __syncthreads();
        if (c < NCHUNK - 1) sstoreA();
    }

#pragma unroll
    for (int mt = 0; mt < 2; mt++) {
#pragma unroll
        for (int nt = 0; nt < 8; nt++) {
            int row  = (int)m0 + wm * 32 + mt * 16 + (lane >> 2);
            int coll = wn * 64 + nt * 8 + (lane & 3) * 2;
            int gcol = ny * 128 + coll;
            float b0 = sbp[coll], b1 = sbp[coll + 1];
            float2 v0 = make_float2(acc[mt][nt][0] + b0, acc[mt][nt][1] + b1);
            float2 v1 = make_float2(acc[mt][nt][2] + b0, acc[mt][nt][3] + b1);
            *(float2*)(g_xproj + (size_t)row * RDIM + gcol) = v0;
            *(float2*)(g_xproj + (size_t)(row + 8) * RDIM + gcol) = v1;
        }
    }
}

// ============================================================================
// Router (tensorized): ut = [h|xp] @ [A;Bm] via mma.sync bf16 3-pass,
// then h_new (transposed in smem), logits, temporal bias, top-2, softmax.
// CTA: M=64 x N=256, K=512 (8 chunks), 8 warps (warp tile 16x128), grid 1024.
// smem overlay:
//   mainloop: [0,1024) tau | [1024,1280) bg | [2048,18432) A hi/lo
//             [18432, 149504) B stages (2 x 65536)
//   epilogue: [2048,71680) hnt[256][68] | [71680,137216) Wgs[256][64]
//             [137216,154624) lg[64][68]
// ============================================================================
#define R_OFF_A    2048
#define R_BST(s)   (18432 + (s) * 65536)
#define R_OFF_HNT  2048
#define R_OFF_WGS  71680
#define R_OFF_LG   137216
#define R_SMEM     154624

__global__ void __launch_bounds__(256, 1)
router_mma_kernel(const float* __restrict__ h, const int* __restrict__ prev_sel,
                  const float* __restrict__ tau,
                  const float* __restrict__ Wg, const float* __restrict__ bg,
                  float* __restrict__ out)
{
    extern __shared__ __align__(1024) char sm[];
    const uint32_t sb = smem_u32(sm);
    float* staus = (float*)sm;
    float* bgs   = (float*)(sm + 1024);
    const int tid  = threadIdx.x;
    const int lane = tid & 31;
    const int wid  = tid >> 5;
    const int wm   = wid & 3;            // 4 warps over M: 16 rows each
    const int wn   = wid >> 2;           // 2 warps over N: 128 cols each
    const size_t m0 = (size_t)blockIdx.x * 64;

    staus[tid] = tau[tid & 255];
    if (tid < EXP) bgs[tid] = bg[tid];

    // ldmatrix lane addressing
    const int j = lane >> 3;
    const int a_rloc = (lane & 7) + (j & 1) * 8;
    const int a_kadd = (j >> 1) * 16;
    const int a_row0 = wm * 16 + a_rloc;
    const uint32_t a_xp    = (uint32_t)((a_row0 & 7) << 4);
    const uint32_t aHiBase = sb + R_OFF_A + a_row0 * 128;
    const int b_nloc = (lane & 7) + (j >> 1) * 8;
    const int b_kadd = (j & 1) * 16;
    const uint32_t b_xp = (uint32_t)((lane & 7) << 4);

    // A gload/sstore mapping: 64 rows x 64 k fp32; 4 float4 per thread
    const int r0 = tid >> 4;            // 0..15
    const int q  = tid & 15;

    float acc[16][4];
#pragma unroll
    for (int b = 0; b < 16; b++)
#pragma unroll
        for (int d = 0; d < 4; d++) acc[b][d] = 0.0f;

    float4 af[4];

    auto gloadA = [&](int c) {
        const float* src = (c < 4) ? (h + (m0 + r0) * RDIM + c * KCH + q * 4)
                                   : (g_xproj + (m0 + r0) * RDIM + (c - 4) * KCH + q * 4);
#pragma unroll
        for (int i = 0; i < 4; i++)
            af[i] = *(const float4*)(src + (size_t)i * 16 * RDIM);
    };
    auto sstoreA = [&]() {
#pragma unroll
        for (int i = 0; i < 4; i++) {
            uint32_t h01, l01, h23, l23;
            split2(af[i].x, af[i].y, h01, l01);
            split2(af[i].z, af[i].w, h23, l23);
            int r = r0 + 16 * i;
            uint32_t off = (uint32_t)(r * 128 + ((q * 8) ^ ((r & 7) << 4)));
            *(uint2*)(sm + R_OFF_A + off)        = make_uint2(h01, h23);
            *(uint2*)(sm + R_OFF_A + 8192 + off) = make_uint2(l01, l23);
        }
    };
    auto cpB = [&](int c, int s) {
        uint32_t dst = sb + R_BST(s);
#pragma unroll
        for (int i = 0; i < 8; i++) {
            int e = tid + i * 256;            // 0..2047
            int nb = e >> 10, jj = e & 1023;
            const uint4* srcH = g_Rhi + (size_t)(nb * 8 + c) * 1024 + jj;
            const uint4* srcL = g_Rlo + (size_t)(nb * 8 + c) * 1024 + jj;
            cpasync16(dst + e * 16, srcH);
            cpasync16(dst + 32768 + e * 16, srcL);
        }
        cpcommit();
    };
    auto compute = [&](int s) {
        const uint32_t sB = sb + R_BST(s) + wn * 16384;
#pragma unroll
        for (int ks = 0; ks < 4; ks++) {
            const uint32_t kb = ks * 32;
            const uint32_t akt = (kb + a_kadd) ^ a_xp;
            uint32_t aH[4], aL[4];
            ldsm4(aH, aHiBase + akt);
            ldsm4(aL, aHiBase + 8192 + akt);
            const uint32_t bkt = (kb + b_kadd) ^ b_xp;
#pragma unroll
            for (int half = 0; half < 2; half++) {
                uint32_t bH[8][2], bL[8][2];
#pragma unroll
                for (int p = 0; p < 4; p++) {
                    uint32_t rr[4];
                    uint32_t rowb = (uint32_t)(((half * 4 + p) * 16 + b_nloc) * 128);
                    ldsm4(rr, sB + rowb + bkt);
                    bH[2 * p][0] = rr[0]; bH[2 * p][1] = rr[1];
                    bH[2 * p + 1][0] = rr[2]; bH[2 * p + 1][1] = rr[3];
                    ldsm4(rr, sB + 32768 + rowb + bkt);
                    bL[2 * p][0] = rr[0]; bL[2 * p][1] = rr[1];
                    bL[2 * p + 1][0] = rr[2]; bL[2 * p + 1][1] = rr[3];
                }
#pragma unroll
                for (int p = 0; p < 8; p++) {
                    int nt = half * 8 + p;
                    mma_bf16(acc[nt], aH, bH[p]);
                    mma_bf16(acc[nt], aH, bL[p]);
                    mma_bf16(acc[nt], aL, bH[p]);
                }
            }
        }
    };

    gloadA(0);
    cpB(0, 0);
    sstoreA();

    for (int c = 0; c < 8; c++) {
        if (c < 7) {
            gloadA(c + 1);
            cpB(c + 1, (c + 1) & 1);
        }
        if (c < 7) cpwait<1>(); else cpwait<0>();
        __syncthreads();
        compute(c & 1);
        __syncthreads();
        if (c < 7) sstoreA();
    }
    __syncthreads();   // all warps done with A/B smem before overlay writes

    // ---- CfC epilogue: h_new transposed into hnt[k][r] (stride 68) ----
    {
        float* hnt = (float*)(sm + R_OFF_HNT);
        const int rloc = wm * 16 + (lane >> 2);
        const size_t grow = m0 + rloc;
#pragma unroll
        for (int nt = 0; nt < 16; nt++) {
            int c0 = wn * 128 + nt * 8 + (lane & 3) * 2;
            float2 h0 = *(const float2*)(h + grow * RDIM + c0);
            float2 h1 = *(const float2*)(h + (grow + 8) * RDIM + c0);
            float t0 = staus[c0], t1 = staus[c0 + 1];
            hnt[c0 * 68 + rloc]           = h0.x + 0.1f * (-h0.x / t0 + tanhf(acc[nt][0]));
            hnt[(c0 + 1) * 68 + rloc]     = h0.y + 0.1f * (-h0.y / t1 + tanhf(acc[nt][1]));
            hnt[c0 * 68 + rloc + 8]       = h1.x + 0.1f * (-h1.x / t0 + tanhf(acc[nt][2]));
            hnt[(c0 + 1) * 68 + rloc + 8] = h1.y + 0.1f * (-h1.y / t1 + tanhf(acc[nt][3]));
        }
    }

    // ---- load Wg into smem ----
    {
        float4* wgs4 = (float4*)(sm + R_OFF_WGS);
#pragma unroll
        for (int i = 0; i < 16; i++) {
            int f = tid + i * 256;
            wgs4[f] = ((const float4*)Wg)[f];
        }
    }
    __syncthreads();

    // ---- logits = h_new @ Wg + bg ----
    {
        const float* hnt = (float*)(sm + R_OFF_HNT);
        float (*Wgs)[64] = (float(*)[64])(sm + R_OFF_WGS);
        float (*lg)[68]  = (float(*)[68])(sm + R_OFF_LG);
        int r2 = tid & 63;
        int cg = tid >> 6;
        float lacc[16];
#pragma unroll
        for (int jj = 0; jj < 16; jj++) lacc[jj] = bgs[cg * 16 + jj];
#pragma unroll 8
        for (int k = 0; k < RDIM; k++) {
            float a = hnt[k * 68 + r2];
            const float* wrow = &Wgs[k][cg * 16];
            float4 w0 = *(const float4*)(wrow + 0);
            float4 w1 = *(const float4*)(wrow + 4);
            float4 w2 = *(const float4*)(wrow + 8);
            float4 w3 = *(const float4*)(wrow + 12);
            lacc[0]  += a * w0.x;  lacc[1]  += a * w0.y;  lacc[2]  += a * w0.z;  lacc[3]  += a * w0.w;
            lacc[4]  += a * w1.x;  lacc[5]  += a * w1.y;  lacc[6]  += a * w1.z;  lacc[7]  += a * w1.w;
            lacc[8]  += a * w2.x;  lacc[9]  += a * w2.y;  lacc[10] += a * w2.z;  lacc[11] += a * w2.w;
            lacc[12] += a * w3.x;  lacc[13] += a * w3.y;  lacc[14] += a * w3.z;  lacc[15] += a * w3.w;
        }
        float* lrow = &lg[r2][cg * 16];
        *(float4*)(lrow + 0)  = make_float4(lacc[0],  lacc[1],  lacc[2],  lacc[3]);
        *(float4*)(lrow + 4)  = make_float4(lacc[4],  lacc[5],  lacc[6],  lacc[7]);
        *(float4*)(lrow + 8)  = make_float4(lacc[8],  lacc[9],  lacc[10], lacc[11]);
        *(float4*)(lrow + 12) = make_float4(lacc[12], lacc[13], lacc[14], lacc[15]);
    }
    __syncthreads();

    // ---- temporal bias + top-2 + softmax ----
    if (tid < 64) {
        float (*lg)[68] = (float(*)[68])(sm + R_OFF_LG);
        size_t grow = m0 + tid;
        int p0 = prev_sel[grow * 2 + 0];
        int p1 = prev_sel[grow * 2 + 1];
        float b1 = -1e30f, b2 = -1e30f;
        int i1 = 0, i2 = 0;
#pragma unroll 8
        for (int e = 0; e < EXP; e++) {
            float v = lg[tid][e];
            if (e == p0 || e == p1) v += 0.1f;
            if (v > b1) { b2 = b1; i2 = i1; b1 = v; i1 = e; }
            else if (v > b2) { b2 = v; i2 = e; }
        }
        float ex = expf(b2 - b1);
        float s  = 1.0f + ex;
        out[grow * 2 + 0] = (float)i1;
        out[grow * 2 + 1] = (float)i2;
        out[2 * (size_t)BATCH + grow * 2 + 0] = 1.0f / s;
        out[2 * (size_t)BATCH + grow * 2 + 1] = ex / s;
    }
}

extern "C" void kernel_launch(void* const* d_in, const int* in_sizes, int n_in,
                              void* d_out, int out_size)
{
    const float* x        = (const float*)d_in[0];
    const float* h        = (const float*)d_in[1];
    const int*   prev_sel = (const int*)d_in[2];
    const float* Wp       = (const float*)d_in[3];
    const float* bp       = (const float*)d_in[4];
    const float* tau      = (const float*)d_in[5];
    const float* Am       = (const float*)d_in[6];
    const float* Bmm      = (const float*)d_in[7];
    const float* Wg       = (const float*)d_in[8];
    const float* bg       = (const float*)d_in[9];
    float* out = (float*)d_out;

    cudaFuncSetAttribute(gemm1_mma_kernel, cudaFuncAttributeMaxDynamicSharedMemorySize, G1_SMEM);
    cudaFuncSetAttribute(router_mma_kernel, cudaFuncAttributeMaxDynamicSharedMemorySize, R_SMEM);

    prep_B_kernel<<<2048, 256>>>(Wp);
    prep_R_kernel<<<256, 256>>>(Am, Bmm);
    gemm1_mma_kernel<<<dim3(512, 2), 256, G1_SMEM>>>(x, bp);
    router_mma_kernel<<<BATCH / 64, 256, R_SMEM>>>(h, prev_sel, tau, Wg, bg, out);
}

// round 5
// speedup vs baseline: 2.3139x; 1.0147x over previous
#include <cuda_runtime.h>
#include <cuda_fp16.h>
#include <math.h>
#include <stdint.h>

#define BATCH 65536
#define HID   4096
#define RDIM  256
#define EXP   64
#define KCH   64
#define NCHUNK 64

#define WSCALE   64.0f       // weight pre-scale (exact power of 2)
#define WUNSCALE 0.015625f   // 1/64

// ------------------------- device scratch -------------------------
__device__ float g_xproj[BATCH * (size_t)RDIM];     // 64 MB
__device__ uint4 g_Bhi[2 * 64 * 1024];              // 2 MB: [nb][chunk] 16KB swizzled tiles (Wp*64)
__device__ uint4 g_Blo[2 * 64 * 1024];              // 2 MB
__device__ uint4 g_Rhi[16 * 1024];                  // 256 KB: [nb][chunk 0..7] ([A;Bm]*64)
__device__ uint4 g_Rlo[16 * 1024];                  // 256 KB

// ------------------------- helpers -------------------------
__device__ __forceinline__ uint32_t smem_u32(const void* p) {
    uint32_t a;
    asm("{ .reg .u64 t; cvta.to.shared.u64 t, %1; cvt.u32.u64 %0, t; }" : "=r"(a) : "l"(p));
    return a;
}
// pack: low half = f16(a), high half = f16(b)
__device__ __forceinline__ uint32_t cvt_f16x2(float a, float b) {
    uint32_t r;
    asm("cvt.rn.f16x2.f32 %0, %1, %2;" : "=r"(r) : "f"(b), "f"(a));
    return r;
}
__device__ __forceinline__ void split2(float a, float b, uint32_t& hi, uint32_t& lo) {
    hi = cvt_f16x2(a, b);
    __half2 hh = *reinterpret_cast<__half2*>(&hi);
    float ha = __low2float(hh);
    float hb = __high2float(hh);
    lo = cvt_f16x2(a - ha, b - hb);
}
__device__ __forceinline__ void ldsm4(uint32_t* r, uint32_t addr) {
    asm volatile("ldmatrix.sync.aligned.m8n8.x4.shared.b16 {%0,%1,%2,%3}, [%4];"
        : "=r"(r[0]), "=r"(r[1]), "=r"(r[2]), "=r"(r[3]) : "r"(addr));
}
__device__ __forceinline__ void mma_f16(float* d, const uint32_t* a, const uint32_t* b) {
    asm volatile("mma.sync.aligned.m16n8k16.row.col.f32.f16.f16.f32 "
        "{%0,%1,%2,%3}, {%4,%5,%6,%7}, {%8,%9}, {%0,%1,%2,%3};"
        : "+f"(d[0]), "+f"(d[1]), "+f"(d[2]), "+f"(d[3])
        : "r"(a[0]), "r"(a[1]), "r"(a[2]), "r"(a[3]), "r"(b[0]), "r"(b[1]));
}
__device__ __forceinline__ void cpasync16(uint32_t dst, const void* src) {
    asm volatile("cp.async.cg.shared.global [%0], [%1], 16;" :: "r"(dst), "l"(src));
}
__device__ __forceinline__ void cpcommit() { asm volatile("cp.async.commit_group;" ::: "memory"); }
template<int N> __device__ __forceinline__ void cpwait() {
    asm volatile("cp.async.wait_group %0;" :: "n"(N) : "memory");
}

// ============================================================================
// Prep: Wp [4096,256] fp32 *64 -> f16 hi/lo transposed [n][k] SW128 tiles
// ============================================================================
__global__ void prep_B_kernel(const float* __restrict__ Wp)
{
    int idx = blockIdx.x * 256 + threadIdx.x;
    int n  = idx & 255;
    int kp = idx >> 8;
    int k0 = kp * 2;
    int c  = k0 >> 6;
    int kl = k0 & 63;
    int nb = n >> 7;
    int r  = n & 127;
    float f0 = Wp[(size_t)k0 * RDIM + n] * WSCALE;
    float f1 = Wp[(size_t)(k0 + 1) * RDIM + n] * WSCALE;
    uint32_t hi, lo;
    split2(f0, f1, hi, lo);
    uint32_t off = (uint32_t)(r * 128 + kl * 2);
    off ^= (off >> 3) & 0x70;
    size_t tile = (size_t)(nb * 64 + c) * 16384;
    *(uint32_t*)((char*)g_Bhi + tile + off) = hi;
    *(uint32_t*)((char*)g_Blo + tile + off) = lo;
}

// ============================================================================
// Prep: [A;Bm] (512x256) fp32 *64 -> f16 hi/lo transposed [n][k] SW128 tiles
// ============================================================================
__global__ void prep_R_kernel(const float* __restrict__ Am, const float* __restrict__ Bmm)
{
    int idx = blockIdx.x * 256 + threadIdx.x;
    int n  = idx & 255;
    int kp = idx >> 8;
    int k0 = kp * 2;
    float f0, f1;
    if (k0 < RDIM) {
        f0 = Am[(size_t)k0 * RDIM + n];
        f1 = Am[(size_t)(k0 + 1) * RDIM + n];
    } else {
        f0 = Bmm[(size_t)(k0 - RDIM) * RDIM + n];
        f1 = Bmm[(size_t)(k0 + 1 - RDIM) * RDIM + n];
    }
    uint32_t hi, lo;
    split2(f0 * WSCALE, f1 * WSCALE, hi, lo);
    int c  = k0 >> 6;
    int kl = k0 & 63;
    int nb = n >> 7;
    int r  = n & 127;
    uint32_t off = (uint32_t)(r * 128 + kl * 2);
    off ^= (off >> 3) & 0x70;
    size_t tile = (size_t)(nb * 8 + c) * 16384;
    *(uint32_t*)((char*)g_Rhi + tile + off) = hi;
    *(uint32_t*)((char*)g_Rlo + tile + off) = lo;
}

// ============================================================================
// GEMM1 via mma.sync f16 (3-pass hi/lo): x_proj = x @ Wp + bp
// CTA: 128(M) x 128(N), grid (512, 2), 256 threads (8 warps, warp tile 32x64)
// smem: [0,1024) bp; A stages @1024 (2 x 32K: hi 16K + lo 16K);
//       B stages @66560 (2 x 32K: hi 16K + lo 16K). Total 132096.
// ============================================================================
#define AST_OFF(s) (1024 + (s) * 32768)
#define BST_OFF(s) (66560 + (s) * 32768)
#define G1_SMEM 132096

__global__ void __launch_bounds__(256, 1)
gemm1_mma_kernel(const float* __restrict__ x, const float* __restrict__ bp)
{
    extern __shared__ __align__(1024) char sm[];
    const uint32_t sb = smem_u32(sm);
    float* sbp = (float*)sm;
    const int tid  = threadIdx.x;
    const int lane = tid & 31;
    const int wid  = tid >> 5;
    const int wm   = wid & 3;
    const int wn   = wid >> 2;
    const int mb   = blockIdx.x;
    const int ny   = blockIdx.y;
    const size_t m0 = (size_t)mb * 128;

    if (tid < 128) sbp[tid] = bp[ny * 128 + tid];

    const int j = lane >> 3;
    const int a_rloc = (lane & 7) + (j & 1) * 8;
    const int a_kadd = (j >> 1) * 16;
    const int a_row0 = wm * 32 + a_rloc;
    const uint32_t a_xp = (uint32_t)((a_row0 & 7) << 4);
    const int b_nloc = (lane & 7) + (j >> 1) * 8;
    const int b_kadd = (j & 1) * 16;
    const uint32_t b_xp = (uint32_t)((lane & 7) << 4);
    uint32_t bRow[4];
#pragma unroll
    for (int p = 0; p < 4; p++) bRow[p] = (uint32_t)((wn * 64 + p * 16 + b_nloc) * 128);

    const int r0 = tid >> 4;
    const int q  = tid & 15;
    const float* xbase = x + (m0 + r0) * HID + q * 4;
    const uint32_t soff0 = (uint32_t)(r0 * 128 + (((q * 8)) ^ ((r0 & 7) << 4)));

    float acc[2][8][4];
#pragma unroll
    for (int a = 0; a < 2; a++)
#pragma unroll
        for (int b = 0; b < 8; b++)
#pragma unroll
            for (int d = 0; d < 4; d++) acc[a][b][d] = 0.0f;

    float4 af[8];

    auto gloadA = [&](int c) {
#pragma unroll
        for (int i = 0; i < 8; i++)
            af[i] = *(const float4*)(xbase + (size_t)i * 16 * HID + c * KCH);
    };
    auto sstoreA = [&](int s) {
        char* dst = sm + AST_OFF(s);
#pragma unroll
        for (int i = 0; i < 8; i++) {
            uint32_t h01, l01, h23, l23;
            split2(af[i].x, af[i].y, h01, l01);
            split2(af[i].z, af[i].w, h23, l23);
            uint32_t off = soff0 + i * 2048;
            *(uint2*)(dst + off)         = make_uint2(h01, h23);
            *(uint2*)(dst + 16384 + off) = make_uint2(l01, l23);
        }
    };
    auto cpB = [&](int c, int s) {
        const uint4* srcH = g_Bhi + (size_t)(ny * 64 + c) * 1024;
        const uint4* srcL = g_Blo + (size_t)(ny * 64 + c) * 1024;
        uint32_t dst = sb + BST_OFF(s);
#pragma unroll
        for (int i = 0; i < 4; i++) {
            int e = tid + i * 256;
            cpasync16(dst + e * 16, srcH + e);
            cpasync16(dst + 16384 + e * 16, srcL + e);
        }
        cpcommit();
    };
    auto compute = [&](int s) {
        const uint32_t aBase = sb + AST_OFF(s) + a_row0 * 128;
        const uint32_t sBhi  = sb + BST_OFF(s);
#pragma unroll
        for (int ks = 0; ks < 4; ks++) {
            const uint32_t kb = ks * 32;
            const uint32_t akt = (kb + a_kadd) ^ a_xp;
            uint32_t aH[2][4], aL[2][4];
            ldsm4(aH[0], aBase + akt);
            ldsm4(aH[1], aBase + 2048 + akt);
            ldsm4(aL[0], aBase + 16384 + akt);
            ldsm4(aL[1], aBase + 16384 + 2048 + akt);
            const uint32_t bkt = (kb + b_kadd) ^ b_xp;
            uint32_t bH[8][2], bL[8][2];
#pragma unroll
            for (int p = 0; p < 4; p++) {
                uint32_t r[4];
                ldsm4(r, sBhi + bRow[p] + bkt);
                bH[2 * p][0] = r[0]; bH[2 * p][1] = r[1];
                bH[2 * p + 1][0] = r[2]; bH[2 * p + 1][1] = r[3];
                ldsm4(r, sBhi + 16384 + bRow[p] + bkt);
                bL[2 * p][0] = r[0]; bL[2 * p][1] = r[1];
                bL[2 * p + 1][0] = r[2]; bL[2 * p + 1][1] = r[3];
            }
#pragma unroll
            for (int mt = 0; mt < 2; mt++) {
#pragma unroll
                for (int nt = 0; nt < 8; nt++) {
                    mma_f16(acc[mt][nt], aH[mt], bH[nt]);
                    mma_f16(acc[mt][nt], aH[mt], bL[nt]);
                    mma_f16(acc[mt][nt], aL[mt], bH[nt]);
                }
            }
        }
    };

    // prologue
    cpB(0, 0);
    gloadA(0);
    sstoreA(0);
    gloadA(1);

    for (int c = 0; c < NCHUNK; c++) {
        cpwait<0>();
        __syncthreads();
        if (c < NCHUNK - 1) cpB(c + 1, (c + 1) & 1);
        compute(c & 1);
        if (c < NCHUNK - 1) sstoreA((c + 1) & 1);
        if (c < NCHUNK - 2) gloadA(c + 2);
    }

    // epilogue: acc * 2^-6 + bp -> g_xproj
#pragma unroll
    for (int mt = 0; mt < 2; mt++) {
#pragma unroll
        for (int nt = 0; nt < 8; nt++) {
            int row  = (int)m0 + wm * 32 + mt * 16 + (lane >> 2);
            int coll = wn * 64 + nt * 8 + (lane & 3) * 2;
            int gcol = ny * 128 + coll;
            float b0 = sbp[coll], b1 = sbp[coll + 1];
            float2 v0 = make_float2(acc[mt][nt][0] * WUNSCALE + b0, acc[mt][nt][1] * WUNSCALE + b1);
            float2 v1 = make_float2(acc[mt][nt][2] * WUNSCALE + b0, acc[mt][nt][3] * WUNSCALE + b1);
            *(float2*)(g_xproj + (size_t)row * RDIM + gcol) = v0;
            *(float2*)(g_xproj + (size_t)(row + 8) * RDIM + gcol) = v1;
        }
    }
}

// ============================================================================
// Router (tensorized, f16 3-pass): ut = [h|xp] @ [A;Bm], CfC, logits, top-2.
// CTA: M=64 x N=256, K=512 (8 chunks), 8 warps (warp tile 16x128), grid 1024.
// smem:
//   mainloop: [0,1024) tau | [1024,1280) bg | A stages @2048 (2 x 16K)
//             B stages @34816 (2 x 64K) -> end 165888
//   epilogue overlay: hnt @2048 (69632) | Wgs @71680 (65536) | lg @137216 (17408)
// ============================================================================
#define R_AST(s)   (2048 + (s) * 16384)
#define R_BST(s)   (34816 + (s) * 65536)
#define R_OFF_HNT  2048
#define R_OFF_WGS  71680
#define R_OFF_LG   137216
#define R_SMEM     165888

__global__ void __launch_bounds__(256, 1)
router_mma_kernel(const float* __restrict__ h, const int* __restrict__ prev_sel,
                  const float* __restrict__ tau,
                  const float* __restrict__ Wg, const float* __restrict__ bg,
                  float* __restrict__ out)
{
    extern __shared__ __align__(1024) char sm[];
    const uint32_t sb = smem_u32(sm);
    float* staus = (float*)sm;
    float* bgs   = (float*)(sm + 1024);
    const int tid  = threadIdx.x;
    const int lane = tid & 31;
    const int wid  = tid >> 5;
    const int wm   = wid & 3;            // 4 warps over M: 16 rows each
    const int wn   = wid >> 2;           // 2 warps over N: 128 cols each
    const size_t m0 = (size_t)blockIdx.x * 64;

    staus[tid] = tau[tid & 255];
    if (tid < EXP) bgs[tid] = bg[tid];

    const int j = lane >> 3;
    const int a_rloc = (lane & 7) + (j & 1) * 8;
    const int a_kadd = (j >> 1) * 16;
    const int a_row0 = wm * 16 + a_rloc;
    const uint32_t a_xp = (uint32_t)((a_row0 & 7) << 4);
    const int b_nloc = (lane & 7) + (j >> 1) * 8;
    const int b_kadd = (j & 1) * 16;
    const uint32_t b_xp = (uint32_t)((lane & 7) << 4);

    const int r0 = tid >> 4;            // 0..15
    const int q  = tid & 15;

    float acc[16][4];
#pragma unroll
    for (int b = 0; b < 16; b++)
#pragma unroll
        for (int d = 0; d < 4; d++) acc[b][d] = 0.0f;

    float4 af[4];

    auto gloadA = [&](int c) {
        const float* src = (c < 4) ? (h + (m0 + r0) * RDIM + c * KCH + q * 4)
                                   : (g_xproj + (m0 + r0) * RDIM + (c - 4) * KCH + q * 4);
#pragma unroll
        for (int i = 0; i < 4; i++)
            af[i] = *(const float4*)(src + (size_t)i * 16 * RDIM);
    };
    auto sstoreA = [&](int s) {
        char* dst = sm + R_AST(s);
#pragma unroll
        for (int i = 0; i < 4; i++) {
            uint32_t h01, l01, h23, l23;
            split2(af[i].x, af[i].y, h01, l01);
            split2(af[i].z, af[i].w, h23, l23);
            int r = r0 + 16 * i;
            uint32_t off = (uint32_t)(r * 128 + ((q * 8) ^ ((r & 7) << 4)));
            *(uint2*)(dst + off)        = make_uint2(h01, h23);
            *(uint2*)(dst + 8192 + off) = make_uint2(l01, l23);
        }
    };
    auto cpB = [&](int c, int s) {
        uint32_t dst = sb + R_BST(s);
#pragma unroll
        for (int i = 0; i < 8; i++) {
            int e = tid + i * 256;
            int nb = e >> 10, jj = e & 1023;
            const uint4* srcH = g_Rhi + (size_t)(nb * 8 + c) * 1024 + jj;
            const uint4* srcL = g_Rlo + (size_t)(nb * 8 + c) * 1024 + jj;
            cpasync16(dst + e * 16, srcH);
            cpasync16(dst + 32768 + e * 16, srcL);
        }
        cpcommit();
    };
    auto compute = [&](int s) {
        const uint32_t aBase = sb + R_AST(s) + a_row0 * 128;
        const uint32_t sB    = sb + R_BST(s) + wn * 16384;
#pragma unroll
        for (int ks = 0; ks < 4; ks++) {
            const uint32_t kb = ks * 32;
            const uint32_t akt = (kb + a_kadd) ^ a_xp;
            uint32_t aH[4], aL[4];
            ldsm4(aH, aBase + akt);
            ldsm4(aL, aBase + 8192 + akt);
            const uint32_t bkt = (kb + b_kadd) ^ b_xp;
#pragma unroll
            for (int half = 0; half < 2; half++) {
                uint32_t bH[8][2], bL[8][2];
#pragma unroll
                for (int p = 0; p < 4; p++) {
                    uint32_t rr[4];
                    uint32_t rowb = (uint32_t)(((half * 4 + p) * 16 + b_nloc) * 128);
                    ldsm4(rr, sB + rowb + bkt);
                    bH[2 * p][0] = rr[0]; bH[2 * p][1] = rr[1];
                    bH[2 * p + 1][0] = rr[2]; bH[2 * p + 1][1] = rr[3];
                    ldsm4(rr, sB + 32768 + rowb + bkt);
                    bL[2 * p][0] = rr[0]; bL[2 * p][1] = rr[1];
                    bL[2 * p + 1][0] = rr[2]; bL[2 * p + 1][1] = rr[3];
                }
#pragma unroll
                for (int p = 0; p < 8; p++) {
                    int nt = half * 8 + p;
                    mma_f16(acc[nt], aH, bH[p]);
                    mma_f16(acc[nt], aH, bL[p]);
                    mma_f16(acc[nt], aL, bH[p]);
                }
            }
        }
    };

    // prologue
    cpB(0, 0);
    gloadA(0);
    sstoreA(0);
    gloadA(1);

    for (int c = 0; c < 8; c++) {
        cpwait<0>();
        __syncthreads();
        if (c < 7) cpB(c + 1, (c + 1) & 1);
        compute(c & 1);
        if (c < 7) sstoreA((c + 1) & 1);
        if (c < 6) gloadA(c + 2);
    }
    __syncthreads();   // all warps done with A/B smem before overlay writes

    // ---- CfC epilogue: h_new transposed into hnt[k][r] (stride 68) ----
    {
        float* hnt = (float*)(sm + R_OFF_HNT);
        const int rloc = wm * 16 + (lane >> 2);
        const size_t grow = m0 + rloc;
#pragma unroll
        for (int nt = 0; nt < 16; nt++) {
            int c0 = wn * 128 + nt * 8 + (lane & 3) * 2;
            float2 h0 = *(const float2*)(h + grow * RDIM + c0);
            float2 h1 = *(const float2*)(h + (grow + 8) * RDIM + c0);
            float t0 = staus[c0], t1 = staus[c0 + 1];
            hnt[c0 * 68 + rloc]           = h0.x + 0.1f * (-h0.x / t0 + tanhf(acc[nt][0] * WUNSCALE));
            hnt[(c0 + 1) * 68 + rloc]     = h0.y + 0.1f * (-h0.y / t1 + tanhf(acc[nt][1] * WUNSCALE));
            hnt[c0 * 68 + rloc + 8]       = h1.x + 0.1f * (-h1.x / t0 + tanhf(acc[nt][2] * WUNSCALE));
            hnt[(c0 + 1) * 68 + rloc + 8] = h1.y + 0.1f * (-h1.y / t1 + tanhf(acc[nt][3] * WUNSCALE));
        }
    }

    // ---- load Wg into smem ----
    {
        float4* wgs4 = (float4*)(sm + R_OFF_WGS);
#pragma unroll
        for (int i = 0; i < 16; i++) {
            int f = tid + i * 256;
            wgs4[f] = ((const float4*)Wg)[f];
        }
    }
    __syncthreads();

    // ---- logits = h_new @ Wg + bg ----
    {
        const float* hnt = (float*)(sm + R_OFF_HNT);
        float (*Wgs)[64] = (float(*)[64])(sm + R_OFF_WGS);
        float (*lg)[68]  = (float(*)[68])(sm + R_OFF_LG);
        int r2 = tid & 63;
        int cg = tid >> 6;
        float lacc[16];
#pragma unroll
        for (int jj = 0; jj < 16; jj++) lacc[jj] = bgs[cg * 16 + jj];
#pragma unroll 8
        for (int k = 0; k < RDIM; k++) {
            float a = hnt[k * 68 + r2];
            const float* wrow = &Wgs[k][cg * 16];
            float4 w0 = *(const float4*)(wrow + 0);
            float4 w1 = *(const float4*)(wrow + 4);
            float4 w2 = *(const float4*)(wrow + 8);
            float4 w3 = *(const float4*)(wrow + 12);
            lacc[0]  += a * w0.x;  lacc[1]  += a * w0.y;  lacc[2]  += a * w0.z;  lacc[3]  += a * w0.w;
            lacc[4]  += a * w1.x;  lacc[5]  += a * w1.y;  lacc[6]  += a * w1.z;  lacc[7]  += a * w1.w;
            lacc[8]  += a * w2.x;  lacc[9]  += a * w2.y;  lacc[10] += a * w2.z;  lacc[11] += a * w2.w;
            lacc[12] += a * w3.x;  lacc[13] += a * w3.y;  lacc[14] += a * w3.z;  lacc[15] += a * w3.w;
        }
        float* lrow = &lg[r2][cg * 16];
        *(float4*)(lrow + 0)  = make_float4(lacc[0],  lacc[1],  lacc[2],  lacc[3]);
        *(float4*)(lrow + 4)  = make_float4(lacc[4],  lacc[5],  lacc[6],  lacc[7]);
        *(float4*)(lrow + 8)  = make_float4(lacc[8],  lacc[9],  lacc[10], lacc[11]);
        *(float4*)(lrow + 12) = make_float4(lacc[12], lacc[13], lacc[14], lacc[15]);
    }
    __syncthreads();

    // ---- temporal bias + top-2 + softmax ----
    if (tid < 64) {
        float (*lg)[68] = (float(*)[68])(sm + R_OFF_LG);
        size_t grow = m0 + tid;
        int p0 = prev_sel[grow * 2 + 0];
        int p1 = prev_sel[grow * 2 + 1];
        float b1 = -1e30f, b2 = -1e30f;
        int i1 = 0, i2 = 0;
#pragma unroll 8
        for (int e = 0; e < EXP; e++) {
            float v = lg[tid][e];
            if (e == p0 || e == p1) v += 0.1f;
            if (v > b1) { b2 = b1; i2 = i1; b1 = v; i1 = e; }
            else if (v > b2) { b2 = v; i2 = e; }
        }
        float ex = expf(b2 - b1);
        float s  = 1.0f + ex;
        out[grow * 2 + 0] = (float)i1;
        out[grow * 2 + 1] = (float)i2;
        out[2 * (size_t)BATCH + grow * 2 + 0] = 1.0f / s;
        out[2 * (size_t)BATCH + grow * 2 + 1] = ex / s;
    }
}

extern "C" void kernel_launch(void* const* d_in, const int* in_sizes, int n_in,
                              void* d_out, int out_size)
{
    const float* x        = (const float*)d_in[0];
    const float* h        = (const float*)d_in[1];
    const int*   prev_sel = (const int*)d_in[2];
    const float* Wp       = (const float*)d_in[3];
    const float* bp       = (const float*)d_in[4];
    const float* tau      = (const float*)d_in[5];
    const float* Am       = (const float*)d_in[6];
    const float* Bmm      = (const float*)d_in[7];
    const float* Wg       = (const float*)d_in[8];
    const float* bg       = (const float*)d_in[9];
    float* out = (float*)d_out;

    cudaFuncSetAttribute(gemm1_mma_kernel, cudaFuncAttributeMaxDynamicSharedMemorySize, G1_SMEM);
    cudaFuncSetAttribute(router_mma_kernel, cudaFuncAttributeMaxDynamicSharedMemorySize, R_SMEM);

    prep_B_kernel<<<2048, 256>>>(Wp);
    prep_R_kernel<<<256, 256>>>(Am, Bmm);
    gemm1_mma_kernel<<<dim3(512, 2), 256, G1_SMEM>>>(x, bp);
    router_mma_kernel<<<BATCH / 64, 256, R_SMEM>>>(h, prev_sel, tau, Wg, bg, out);
}